// round 14
// baseline (speedup 1.0000x reference)
#include <cuda_runtime.h>
#include <cuda_fp16.h>
#include <math.h>
#include <stdint.h>

#define SEQ_L 2048
#define BATCH 8
#define DIM 1024
#define MROWS (SEQ_L * BATCH)   // 16384
#define N3 (3 * DIM)            // 3072
#define LN_EPS 1e-5f

#define CHUNK 32
#define NCHUNK (SEQ_L / CHUNK)  // 64  (= 2*warpSize, required by scanB)
#define BD (BATCH * DIM)        // 8192

// ---------------- scratch (allocation-free) ----------------
__device__ __half g_xn_hf[(size_t)MROWS * DIM];  // fp16 x_norm
__device__ __half g_w_hf[(size_t)N3 * DIM];      // fp16 W
__device__ __half g_u_hf[(size_t)MROWS * DIM];   // u fp16
// f/r interleaved by 4: row*2048 + (d>>2)*8 + (d&3) for f, +4 for r
__device__ __half g_fr[(size_t)MROWS * 2 * DIM];
__device__ float  g_scanP[NCHUNK * BD];
__device__ float  g_scanQ[NCHUNK * BD];
__device__ float  g_cin[NCHUNK * BD];

__device__ __forceinline__ float sigmoid_f(float v) {
    return 1.0f / (1.0f + __expf(-v));
}
__device__ __forceinline__ float tanh_fast(float v) {
    return 1.0f - 2.0f / (1.0f + __expf(2.0f * v));
}

// ---------------------------------------------------------------------------
// Kernel 1: fused LayerNorm (blocks 0..2047) + W->fp16 (blocks 2048..5119)
// ---------------------------------------------------------------------------
#define LN_BLOCKS (MROWS / 8)                 // 2048
#define WCONV_BLOCKS ((N3 * DIM / 4) / 256)   // 3072

__global__ void __launch_bounds__(256) prep_kernel(
    const float* __restrict__ x,
    const float* __restrict__ gamma,
    const float* __restrict__ beta,
    const float* __restrict__ W)
{
    if (blockIdx.x >= LN_BLOCKS) {
        int i = (blockIdx.x - LN_BLOCKS) * blockDim.x + threadIdx.x;
        float4 v = reinterpret_cast<const float4*>(W)[i];
        __half2 h0 = __floats2half2_rn(v.x, v.y);
        __half2 h1 = __floats2half2_rn(v.z, v.w);
        uint2 packed;
        packed.x = *reinterpret_cast<uint32_t*>(&h0);
        packed.y = *reinterpret_cast<uint32_t*>(&h1);
        reinterpret_cast<uint2*>(g_w_hf)[i] = packed;
        return;
    }

    int warp = threadIdx.x >> 5;
    int lane = threadIdx.x & 31;
    int row = blockIdx.x * 8 + warp;

    const float4* xr = reinterpret_cast<const float4*>(x + (size_t)row * DIM);
    float4 v[8];
    #pragma unroll
    for (int j = 0; j < 8; j++) v[j] = xr[lane + j * 32];

    float s = 0.0f, s2 = 0.0f;
    #pragma unroll
    for (int j = 0; j < 8; j++) {
        s  += v[j].x + v[j].y + v[j].z + v[j].w;
        s2 += v[j].x*v[j].x + v[j].y*v[j].y + v[j].z*v[j].z + v[j].w*v[j].w;
    }
    #pragma unroll
    for (int o = 16; o > 0; o >>= 1) {
        s  += __shfl_xor_sync(0xffffffffu, s,  o);
        s2 += __shfl_xor_sync(0xffffffffu, s2, o);
    }
    float mean = s * (1.0f / DIM);
    float var  = s2 * (1.0f / DIM) - mean * mean;
    float inv  = rsqrtf(var + LN_EPS);

    uint2* orow = reinterpret_cast<uint2*>(g_xn_hf + (size_t)row * DIM);
    const float4* gp = reinterpret_cast<const float4*>(gamma);
    const float4* bp = reinterpret_cast<const float4*>(beta);
    #pragma unroll
    for (int j = 0; j < 8; j++) {
        float4 g = gp[lane + j * 32];
        float4 b = bp[lane + j * 32];
        float o0 = (v[j].x - mean) * inv * g.x + b.x;
        float o1 = (v[j].y - mean) * inv * g.y + b.y;
        float o2 = (v[j].z - mean) * inv * g.z + b.z;
        float o3 = (v[j].w - mean) * inv * g.w + b.w;
        __half2 h0 = __floats2half2_rn(o0, o1);
        __half2 h1 = __floats2half2_rn(o2, o3);
        uint2 packed;
        packed.x = *reinterpret_cast<uint32_t*>(&h0);
        packed.y = *reinterpret_cast<uint32_t*>(&h1);
        orow[lane + j * 32] = packed;
    }
}

// ---------------------------------------------------------------------------
// Kernel 2: fp16 mma.sync GEMM (frozen mainloop; epilogue uses fr-interleave)
// ---------------------------------------------------------------------------
#define BM 128
#define BN 128
#define BK 32
#define NSTAGE 5
#define KITER (DIM / BK)              // 32
#define TILE_A_BYTES (BM * BK * 2)
#define TILE_B_BYTES (BN * BK * 2)
#define STAGE_BYTES (TILE_A_BYTES + TILE_B_BYTES)  // 16384
#define GEMM_SMEM (NSTAGE * STAGE_BYTES)           // 81920

__device__ __forceinline__ uint32_t smem_u32(const void* p) {
    uint32_t a;
    asm("{ .reg .u64 t; cvta.to.shared.u64 t, %1; cvt.u32.u64 %0, t; }" : "=r"(a) : "l"(p));
    return a;
}
__device__ __forceinline__ uint32_t sw_off(int row, int c) {
    return (uint32_t)(row * 64 + ((c ^ (row & 3)) << 4));
}
__device__ __forceinline__ void cp_async16(uint32_t smem_addr, const void* gptr) {
    asm volatile("cp.async.cg.shared.global [%0], [%1], 16;"
                 :: "r"(smem_addr), "l"(gptr) : "memory");
}
__device__ __forceinline__ void cp_commit() {
    asm volatile("cp.async.commit_group;" ::: "memory");
}
__device__ __forceinline__ void cp_wait3() {
    asm volatile("cp.async.wait_group 3;" ::: "memory");
}
__device__ __forceinline__ void ldmatrix_x4(uint32_t* r, uint32_t addr) {
    asm volatile("ldmatrix.sync.aligned.m8n8.x4.shared.b16 {%0,%1,%2,%3}, [%4];"
                 : "=r"(r[0]), "=r"(r[1]), "=r"(r[2]), "=r"(r[3]) : "r"(addr));
}
__device__ __forceinline__ void mma16816(float* d, const uint32_t* a, const uint32_t* b) {
    asm volatile("mma.sync.aligned.m16n8k16.row.col.f32.f16.f16.f32 "
                 "{%0,%1,%2,%3}, {%4,%5,%6,%7}, {%8,%9}, {%0,%1,%2,%3};"
                 : "+f"(d[0]), "+f"(d[1]), "+f"(d[2]), "+f"(d[3])
                 : "r"(a[0]), "r"(a[1]), "r"(a[2]), "r"(a[3]), "r"(b[0]), "r"(b[1]));
}

__global__ void __launch_bounds__(256, 2) gemm_kernel()
{
    extern __shared__ char smem[];
    const int tid  = threadIdx.x;
    const int wid  = tid >> 5;
    const int lane = tid & 31;
    const int bn = blockIdx.x;   // 0..23
    const int bm = blockIdx.y;   // 0..127

    const int wm = wid & 3;
    const int wn = wid >> 2;

    const __half* Abase = g_xn_hf + (size_t)(bm * BM) * DIM;
    const __half* Bbase = g_w_hf  + (size_t)(bn * BN) * DIM;

    const int r0 = tid >> 1;
    const int cpair = (tid & 1) * 2;

    auto load_stage = [&](int kt, int st) {
        char* sa = smem + st * STAGE_BYTES;
        char* sb = sa + TILE_A_BYTES;
        const __half* ag = Abase + (size_t)r0 * DIM + kt * BK + cpair * 8;
        const __half* bg = Bbase + (size_t)r0 * DIM + kt * BK + cpair * 8;
        cp_async16(smem_u32(sa + sw_off(r0, cpair)),     ag);
        cp_async16(smem_u32(sa + sw_off(r0, cpair + 1)), ag + 8);
        cp_async16(smem_u32(sb + sw_off(r0, cpair)),     bg);
        cp_async16(smem_u32(sb + sw_off(r0, cpair + 1)), bg + 8);
    };

    float acc[2][8][4];
    #pragma unroll
    for (int i = 0; i < 2; i++)
        #pragma unroll
        for (int j = 0; j < 8; j++)
            #pragma unroll
            for (int k = 0; k < 4; k++) acc[i][j][k] = 0.0f;

    #pragma unroll
    for (int s = 0; s < NSTAGE - 1; s++) { load_stage(s, s); cp_commit(); }

    const int a_row_in_tile = lane & 15;
    const int a_chunk_half  = lane >> 4;
    const int b_row_in_pair = ((lane >> 4) << 3) + (lane & 7);
    const int b_chunk_half  = (lane >> 3) & 1;

    for (int kt = 0; kt < KITER; kt++) {
        cp_wait3();
        __syncthreads();

        int nkt = kt + NSTAGE - 1;
        if (nkt < KITER) load_stage(nkt, nkt % NSTAGE);
        cp_commit();

        char* sa = smem + (kt % NSTAGE) * STAGE_BYTES;
        char* sb = sa + TILE_A_BYTES;

        #pragma unroll
        for (int ks = 0; ks < 2; ks++) {
            uint32_t afr[2][4];
            #pragma unroll
            for (int mt = 0; mt < 2; mt++) {
                int row = wm * 32 + mt * 16 + a_row_in_tile;
                int c   = ks * 2 + a_chunk_half;
                ldmatrix_x4(afr[mt], smem_u32(sa + sw_off(row, c)));
            }
            uint32_t bfr[8][2];
            #pragma unroll
            for (int np = 0; np < 4; np++) {
                uint32_t r[4];
                int row = wn * 64 + np * 16 + b_row_in_pair;
                int c   = ks * 2 + b_chunk_half;
                ldmatrix_x4(r, smem_u32(sb + sw_off(row, c)));
                bfr[np * 2 + 0][0] = r[0]; bfr[np * 2 + 0][1] = r[1];
                bfr[np * 2 + 1][0] = r[2]; bfr[np * 2 + 1][1] = r[3];
            }
            #pragma unroll
            for (int mt = 0; mt < 2; mt++)
                #pragma unroll
                for (int nt = 0; nt < 8; nt++)
                    mma16816(acc[mt][nt], afr[mt], bfr[nt]);
        }
    }

    // epilogue: bn<8 -> u (fp16); bn 8..15 -> f; bn 16..23 -> r (interleaved-by-4)
    const int crow = bm * BM + wm * 32 + (lane >> 2);
    const int ccol_in = wn * 64 + (lane & 3) * 2;
    if (bn < 8) {
        const int ccol = bn * BN + ccol_in;
        #pragma unroll
        for (int mt = 0; mt < 2; mt++)
            #pragma unroll
            for (int nt = 0; nt < 8; nt++) {
                __half* p0 = g_u_hf + (size_t)(crow + mt * 16)     * DIM + ccol + nt * 8;
                __half* p1 = g_u_hf + (size_t)(crow + mt * 16 + 8) * DIM + ccol + nt * 8;
                *reinterpret_cast<__half2*>(p0) = __floats2half2_rn(acc[mt][nt][0], acc[mt][nt][1]);
                *reinterpret_cast<__half2*>(p1) = __floats2half2_rn(acc[mt][nt][2], acc[mt][nt][3]);
            }
    } else {
        const int is_r = (bn >= 16) ? 4 : 0;
        const int dbase = (bn - (is_r ? 16 : 8)) * BN + ccol_in;   // logical f/r col
        #pragma unroll
        for (int mt = 0; mt < 2; mt++)
            #pragma unroll
            for (int nt = 0; nt < 8; nt++) {
                int dv = dbase + nt * 8;
                size_t off = ((size_t)(dv >> 2) << 3) + (dv & 3) + is_r;
                __half* p0 = g_fr + (size_t)(crow + mt * 16)     * (2 * DIM) + off;
                __half* p1 = g_fr + (size_t)(crow + mt * 16 + 8) * (2 * DIM) + off;
                *reinterpret_cast<__half2*>(p0) = __floats2half2_rn(acc[mt][nt][0], acc[mt][nt][1]);
                *reinterpret_cast<__half2*>(p1) = __floats2half2_rn(acc[mt][nt][2], acc[mt][nt][3]);
            }
    }
}

// ---------------------------------------------------------------------------
// Kernel 3a: per-chunk (P,q).  x4, 128-thread blocks -> grid 1024.
// ---------------------------------------------------------------------------
__global__ void __launch_bounds__(128) scanA_kernel()
{
    int gid4 = blockIdx.x * blockDim.x + threadIdx.x;
    int chunk = gid4 / (BD / 4);
    int cd4 = gid4 % (BD / 4);
    int b = cd4 / (DIM / 4);
    int d = (cd4 % (DIM / 4)) * 4;

    float P[4] = {1.0f, 1.0f, 1.0f, 1.0f};
    float q[4] = {0.0f, 0.0f, 0.0f, 0.0f};
    int l0 = chunk * CHUNK;
    #pragma unroll 4
    for (int i = 0; i < CHUNK; i++) {
        int m = (l0 + i) * BATCH + b;
        uint2 uraw = *reinterpret_cast<const uint2*>(g_u_hf + (size_t)m * DIM + d);
        uint2 fraw = *reinterpret_cast<const uint2*>(g_fr + (size_t)m * (2 * DIM) + ((d >> 2) << 3));
        float2 u01 = __half22float2(*reinterpret_cast<__half2*>(&uraw.x));
        float2 u23 = __half22float2(*reinterpret_cast<__half2*>(&uraw.y));
        float2 f01 = __half22float2(*reinterpret_cast<__half2*>(&fraw.x));
        float2 f23 = __half22float2(*reinterpret_cast<__half2*>(&fraw.y));
        float uv[4] = {u01.x, u01.y, u23.x, u23.y};
        float fv[4] = {f01.x, f01.y, f23.x, f23.y};
        #pragma unroll
        for (int j = 0; j < 4; j++) {
            float fg = sigmoid_f(fv[j]);
            q[j] = fg * q[j] + (1.0f - fg) * uv[j];
            P[j] *= fg;
        }
    }
    int o = chunk * BD + b * DIM + d;
    *reinterpret_cast<float4*>(g_scanP + o) = make_float4(P[0], P[1], P[2], P[3]);
    *reinterpret_cast<float4*>(g_scanQ + o) = make_float4(q[0], q[1], q[2], q[3]);
}

// ---------------------------------------------------------------------------
// Kernel 3b: warp-per-channel affine scan, smem-staged for coalescing.
// Block: 256 threads = 8 warps = 8 channels. grid = BD/8 = 1024.
// ---------------------------------------------------------------------------
#define SB_CH 8
#define SB_PAD 9

__global__ void __launch_bounds__(256) scanB_kernel(
    const float* __restrict__ c0, float* __restrict__ out, int write_last_c)
{
    __shared__ float sP[NCHUNK * SB_PAD];
    __shared__ float sQ[NCHUNK * SB_PAD];
    __shared__ float sC[NCHUNK * SB_PAD];

    int tid = threadIdx.x;
    int ch_base = blockIdx.x * SB_CH;

    // cooperative coalesced load: 64 chunks x 8 channels
    for (int i = tid; i < NCHUNK * SB_CH; i += 256) {
        int k = i >> 3, c = i & 7;
        sP[k * SB_PAD + c] = g_scanP[(size_t)k * BD + ch_base + c];
        sQ[k * SB_PAD + c] = g_scanQ[(size_t)k * BD + ch_base + c];
    }
    __syncthreads();

    int warp = tid >> 5;
    int lane = tid & 31;
    int c = warp;          // channel within block
    int k0 = 2 * lane;

    float P0 = sP[k0 * SB_PAD + c];
    float Q0 = sQ[k0 * SB_PAD + c];
    float P1 = sP[(k0 + 1) * SB_PAD + c];
    float Q1 = sQ[(k0 + 1) * SB_PAD + c];

    float sp = P1 * P0;
    float sq = P1 * Q0 + Q1;

    #pragma unroll
    for (int o = 1; o < 32; o <<= 1) {
        float pp = __shfl_up_sync(0xffffffffu, sp, o);
        float pq = __shfl_up_sync(0xffffffffu, sq, o);
        if (lane >= o) {
            sq = sp * pq + sq;
            sp = sp * pp;
        }
    }
    float ep = __shfl_up_sync(0xffffffffu, sp, 1);
    float eq = __shfl_up_sync(0xffffffffu, sq, 1);
    if (lane == 0) { ep = 1.0f; eq = 0.0f; }

    float cv = c0[ch_base + c];
    float cl = ep * cv + eq;
    sC[k0 * SB_PAD + c] = cl;
    sC[(k0 + 1) * SB_PAD + c] = P0 * cl + Q0;

    if (write_last_c && lane == 31)
        out[(size_t)MROWS * DIM + ch_base + c] = sp * cv + sq;

    __syncthreads();
    for (int i = tid; i < NCHUNK * SB_CH; i += 256) {
        int k = i >> 3, cc = i & 7;
        g_cin[(size_t)k * BD + ch_base + cc] = sC[k * SB_PAD + cc];
    }
}

// ---------------------------------------------------------------------------
// Kernel 3c: apply pass.  x4, 128-thread blocks -> grid 1024.
// ---------------------------------------------------------------------------
__global__ void __launch_bounds__(128) scanC_kernel(
    const float* __restrict__ x, float* __restrict__ out)
{
    int gid4 = blockIdx.x * blockDim.x + threadIdx.x;
    int chunk = gid4 / (BD / 4);
    int cd4 = gid4 % (BD / 4);
    int b = cd4 / (DIM / 4);
    int d = (cd4 % (DIM / 4)) * 4;

    int ci = chunk * BD + b * DIM + d;
    float4 cv4 = *reinterpret_cast<const float4*>(g_cin + ci);
    float cv[4] = {cv4.x, cv4.y, cv4.z, cv4.w};
    int l0 = chunk * CHUNK;
    #pragma unroll 4
    for (int i = 0; i < CHUNK; i++) {
        int m = (l0 + i) * BATCH + b;
        uint2 uraw = *reinterpret_cast<const uint2*>(g_u_hf + (size_t)m * DIM + d);
        uint4 frraw = *reinterpret_cast<const uint4*>(g_fr + (size_t)m * (2 * DIM) + ((d >> 2) << 3));
        uint2 nraw = *reinterpret_cast<const uint2*>(g_xn_hf + (size_t)m * DIM + d);
        size_t xi = (size_t)m * DIM + d;
        float4 xv = *reinterpret_cast<const float4*>(x + xi);

        float2 u01 = __half22float2(*reinterpret_cast<__half2*>(&uraw.x));
        float2 u23 = __half22float2(*reinterpret_cast<__half2*>(&uraw.y));
        float2 f01 = __half22float2(*reinterpret_cast<__half2*>(&frraw.x));
        float2 f23 = __half22float2(*reinterpret_cast<__half2*>(&frraw.y));
        float2 r01 = __half22float2(*reinterpret_cast<__half2*>(&frraw.z));
        float2 r23 = __half22float2(*reinterpret_cast<__half2*>(&frraw.w));
        float2 n01 = __half22float2(*reinterpret_cast<__half2*>(&nraw.x));
        float2 n23 = __half22float2(*reinterpret_cast<__half2*>(&nraw.y));

        float uv[4] = {u01.x, u01.y, u23.x, u23.y};
        float fv[4] = {f01.x, f01.y, f23.x, f23.y};
        float rv[4] = {r01.x, r01.y, r23.x, r23.y};
        float nv[4] = {n01.x, n01.y, n23.x, n23.y};
        float xvv[4] = {xv.x, xv.y, xv.z, xv.w};
        float ov[4];
        #pragma unroll
        for (int j = 0; j < 4; j++) {
            float fg = sigmoid_f(fv[j]);
            cv[j] = fg * cv[j] + (1.0f - fg) * uv[j];
            float rg = sigmoid_f(rv[j]);
            float h = rg * tanh_fast(cv[j]) + (1.0f - rg) * nv[j];
            ov[j] = xvv[j] + h;
        }
        *reinterpret_cast<float4*>(out + xi) = make_float4(ov[0], ov[1], ov[2], ov[3]);
    }
}

// ---------------------------------------------------------------------------
// Launch
// ---------------------------------------------------------------------------
extern "C" void kernel_launch(void* const* d_in, const int* in_sizes, int n_in,
                              void* d_out, int out_size)
{
    const float* x     = (const float*)d_in[0];
    const float* c0    = (const float*)d_in[1];
    const float* W     = (const float*)d_in[2];
    const float* gamma = (const float*)d_in[3];
    const float* beta  = (const float*)d_in[4];
    float* out = (float*)d_out;

    int write_last_c = (out_size >= MROWS * DIM + BD) ? 1 : 0;

    static int configured = 0;
    if (!configured) {
        cudaFuncSetAttribute(gemm_kernel, cudaFuncAttributeMaxDynamicSharedMemorySize,
                             GEMM_SMEM);
        configured = 1;
    }

    prep_kernel<<<LN_BLOCKS + WCONV_BLOCKS, 256>>>(x, gamma, beta, W);
    gemm_kernel<<<dim3(N3 / BN, MROWS / BM), 256, GEMM_SMEM>>>();
    scanA_kernel<<<(NCHUNK * BD / 4) / 128, 128>>>();
    scanB_kernel<<<BD / SB_CH, 256>>>(c0, out, write_last_c);
    scanC_kernel<<<(NCHUNK * BD / 4) / 128, 128>>>(x, out);
}

// round 15
// speedup vs baseline: 1.0081x; 1.0081x over previous
#include <cuda_runtime.h>
#include <cuda_fp16.h>
#include <math.h>
#include <stdint.h>

#define SEQ_L 2048
#define BATCH 8
#define DIM 1024
#define MROWS (SEQ_L * BATCH)   // 16384
#define N3 (3 * DIM)            // 3072
#define LN_EPS 1e-5f

#define CHUNK 32
#define NCHUNK (SEQ_L / CHUNK)  // 64  (= 2*warpSize, required by scanB)
#define BD (BATCH * DIM)        // 8192

// ---------------- scratch (allocation-free) ----------------
__device__ __half g_xn_hf[(size_t)MROWS * DIM];  // fp16 x_norm
__device__ __half g_w_hf[(size_t)N3 * DIM];      // fp16 W
__device__ __half g_u_hf[(size_t)MROWS * DIM];   // u fp16
__device__ __half g_fr[(size_t)MROWS * 2 * DIM]; // f,r fp16 (two contiguous halves per row)
__device__ float  g_scanP[NCHUNK * BD];
__device__ float  g_scanQ[NCHUNK * BD];
__device__ float  g_cin[NCHUNK * BD];

__device__ __forceinline__ float sigmoid_f(float v) {
    return 1.0f / (1.0f + __expf(-v));
}
__device__ __forceinline__ float tanh_fast(float v) {
    return 1.0f - 2.0f / (1.0f + __expf(2.0f * v));
}

// ---------------------------------------------------------------------------
// Kernel 1: fused LayerNorm (blocks 0..2047) + W->fp16 (blocks 2048..5119)
// ---------------------------------------------------------------------------
#define LN_BLOCKS (MROWS / 8)                 // 2048
#define WCONV_BLOCKS ((N3 * DIM / 4) / 256)   // 3072

__global__ void __launch_bounds__(256) prep_kernel(
    const float* __restrict__ x,
    const float* __restrict__ gamma,
    const float* __restrict__ beta,
    const float* __restrict__ W)
{
    if (blockIdx.x >= LN_BLOCKS) {
        int i = (blockIdx.x - LN_BLOCKS) * blockDim.x + threadIdx.x;
        float4 v = reinterpret_cast<const float4*>(W)[i];
        __half2 h0 = __floats2half2_rn(v.x, v.y);
        __half2 h1 = __floats2half2_rn(v.z, v.w);
        uint2 packed;
        packed.x = *reinterpret_cast<uint32_t*>(&h0);
        packed.y = *reinterpret_cast<uint32_t*>(&h1);
        reinterpret_cast<uint2*>(g_w_hf)[i] = packed;
        return;
    }

    int warp = threadIdx.x >> 5;
    int lane = threadIdx.x & 31;
    int row = blockIdx.x * 8 + warp;

    const float4* xr = reinterpret_cast<const float4*>(x + (size_t)row * DIM);
    float4 v[8];
    #pragma unroll
    for (int j = 0; j < 8; j++) v[j] = xr[lane + j * 32];

    float s = 0.0f, s2 = 0.0f;
    #pragma unroll
    for (int j = 0; j < 8; j++) {
        s  += v[j].x + v[j].y + v[j].z + v[j].w;
        s2 += v[j].x*v[j].x + v[j].y*v[j].y + v[j].z*v[j].z + v[j].w*v[j].w;
    }
    #pragma unroll
    for (int o = 16; o > 0; o >>= 1) {
        s  += __shfl_xor_sync(0xffffffffu, s,  o);
        s2 += __shfl_xor_sync(0xffffffffu, s2, o);
    }
    float mean = s * (1.0f / DIM);
    float var  = s2 * (1.0f / DIM) - mean * mean;
    float inv  = rsqrtf(var + LN_EPS);

    uint2* orow = reinterpret_cast<uint2*>(g_xn_hf + (size_t)row * DIM);
    const float4* gp = reinterpret_cast<const float4*>(gamma);
    const float4* bp = reinterpret_cast<const float4*>(beta);
    #pragma unroll
    for (int j = 0; j < 8; j++) {
        float4 g = gp[lane + j * 32];
        float4 b = bp[lane + j * 32];
        float o0 = (v[j].x - mean) * inv * g.x + b.x;
        float o1 = (v[j].y - mean) * inv * g.y + b.y;
        float o2 = (v[j].z - mean) * inv * g.z + b.z;
        float o3 = (v[j].w - mean) * inv * g.w + b.w;
        __half2 h0 = __floats2half2_rn(o0, o1);
        __half2 h1 = __floats2half2_rn(o2, o3);
        uint2 packed;
        packed.x = *reinterpret_cast<uint32_t*>(&h0);
        packed.y = *reinterpret_cast<uint32_t*>(&h1);
        orow[lane + j * 32] = packed;
    }
}

// ---------------------------------------------------------------------------
// Kernel 2: fp16 mma.sync GEMM (frozen best-measured configuration)
// ---------------------------------------------------------------------------
#define BM 128
#define BN 128
#define BK 32
#define NSTAGE 5
#define KITER (DIM / BK)              // 32
#define TILE_A_BYTES (BM * BK * 2)
#define TILE_B_BYTES (BN * BK * 2)
#define STAGE_BYTES (TILE_A_BYTES + TILE_B_BYTES)  // 16384
#define GEMM_SMEM (NSTAGE * STAGE_BYTES)           // 81920

__device__ __forceinline__ uint32_t smem_u32(const void* p) {
    uint32_t a;
    asm("{ .reg .u64 t; cvta.to.shared.u64 t, %1; cvt.u32.u64 %0, t; }" : "=r"(a) : "l"(p));
    return a;
}
__device__ __forceinline__ uint32_t sw_off(int row, int c) {
    return (uint32_t)(row * 64 + ((c ^ (row & 3)) << 4));
}
__device__ __forceinline__ void cp_async16(uint32_t smem_addr, const void* gptr) {
    asm volatile("cp.async.cg.shared.global [%0], [%1], 16;"
                 :: "r"(smem_addr), "l"(gptr) : "memory");
}
__device__ __forceinline__ void cp_commit() {
    asm volatile("cp.async.commit_group;" ::: "memory");
}
__device__ __forceinline__ void cp_wait3() {
    asm volatile("cp.async.wait_group 3;" ::: "memory");
}
__device__ __forceinline__ void ldmatrix_x4(uint32_t* r, uint32_t addr) {
    asm volatile("ldmatrix.sync.aligned.m8n8.x4.shared.b16 {%0,%1,%2,%3}, [%4];"
                 : "=r"(r[0]), "=r"(r[1]), "=r"(r[2]), "=r"(r[3]) : "r"(addr));
}
__device__ __forceinline__ void mma16816(float* d, const uint32_t* a, const uint32_t* b) {
    asm volatile("mma.sync.aligned.m16n8k16.row.col.f32.f16.f16.f32 "
                 "{%0,%1,%2,%3}, {%4,%5,%6,%7}, {%8,%9}, {%0,%1,%2,%3};"
                 : "+f"(d[0]), "+f"(d[1]), "+f"(d[2]), "+f"(d[3])
                 : "r"(a[0]), "r"(a[1]), "r"(a[2]), "r"(a[3]), "r"(b[0]), "r"(b[1]));
}

__global__ void __launch_bounds__(256, 2) gemm_kernel()
{
    extern __shared__ char smem[];
    const int tid  = threadIdx.x;
    const int wid  = tid >> 5;
    const int lane = tid & 31;
    const int bn = blockIdx.x;   // 0..23
    const int bm = blockIdx.y;   // 0..127

    const int wm = wid & 3;
    const int wn = wid >> 2;

    const __half* Abase = g_xn_hf + (size_t)(bm * BM) * DIM;
    const __half* Bbase = g_w_hf  + (size_t)(bn * BN) * DIM;

    const int r0 = tid >> 1;
    const int cpair = (tid & 1) * 2;

    auto load_stage = [&](int kt, int st) {
        char* sa = smem + st * STAGE_BYTES;
        char* sb = sa + TILE_A_BYTES;
        const __half* ag = Abase + (size_t)r0 * DIM + kt * BK + cpair * 8;
        const __half* bg = Bbase + (size_t)r0 * DIM + kt * BK + cpair * 8;
        cp_async16(smem_u32(sa + sw_off(r0, cpair)),     ag);
        cp_async16(smem_u32(sa + sw_off(r0, cpair + 1)), ag + 8);
        cp_async16(smem_u32(sb + sw_off(r0, cpair)),     bg);
        cp_async16(smem_u32(sb + sw_off(r0, cpair + 1)), bg + 8);
    };

    float acc[2][8][4];
    #pragma unroll
    for (int i = 0; i < 2; i++)
        #pragma unroll
        for (int j = 0; j < 8; j++)
            #pragma unroll
            for (int k = 0; k < 4; k++) acc[i][j][k] = 0.0f;

    #pragma unroll
    for (int s = 0; s < NSTAGE - 1; s++) { load_stage(s, s); cp_commit(); }

    const int a_row_in_tile = lane & 15;
    const int a_chunk_half  = lane >> 4;
    const int b_row_in_pair = ((lane >> 4) << 3) + (lane & 7);
    const int b_chunk_half  = (lane >> 3) & 1;

    for (int kt = 0; kt < KITER; kt++) {
        cp_wait3();
        __syncthreads();

        int nkt = kt + NSTAGE - 1;
        if (nkt < KITER) load_stage(nkt, nkt % NSTAGE);
        cp_commit();

        char* sa = smem + (kt % NSTAGE) * STAGE_BYTES;
        char* sb = sa + TILE_A_BYTES;

        #pragma unroll
        for (int ks = 0; ks < 2; ks++) {
            uint32_t afr[2][4];
            #pragma unroll
            for (int mt = 0; mt < 2; mt++) {
                int row = wm * 32 + mt * 16 + a_row_in_tile;
                int c   = ks * 2 + a_chunk_half;
                ldmatrix_x4(afr[mt], smem_u32(sa + sw_off(row, c)));
            }
            uint32_t bfr[8][2];
            #pragma unroll
            for (int np = 0; np < 4; np++) {
                uint32_t r[4];
                int row = wn * 64 + np * 16 + b_row_in_pair;
                int c   = ks * 2 + b_chunk_half;
                ldmatrix_x4(r, smem_u32(sb + sw_off(row, c)));
                bfr[np * 2 + 0][0] = r[0]; bfr[np * 2 + 0][1] = r[1];
                bfr[np * 2 + 1][0] = r[2]; bfr[np * 2 + 1][1] = r[3];
            }
            #pragma unroll
            for (int mt = 0; mt < 2; mt++)
                #pragma unroll
                for (int nt = 0; nt < 8; nt++)
                    mma16816(acc[mt][nt], afr[mt], bfr[nt]);
        }
    }

    // epilogue: bn<8 -> u (fp16); else f/r (fp16, contiguous halves)
    const int crow = bm * BM + wm * 32 + (lane >> 2);
    const int ccol_in = wn * 64 + (lane & 3) * 2;
    if (bn < 8) {
        const int ccol = bn * BN + ccol_in;
        #pragma unroll
        for (int mt = 0; mt < 2; mt++)
            #pragma unroll
            for (int nt = 0; nt < 8; nt++) {
                __half* p0 = g_u_hf + (size_t)(crow + mt * 16)     * DIM + ccol + nt * 8;
                __half* p1 = g_u_hf + (size_t)(crow + mt * 16 + 8) * DIM + ccol + nt * 8;
                *reinterpret_cast<__half2*>(p0) = __floats2half2_rn(acc[mt][nt][0], acc[mt][nt][1]);
                *reinterpret_cast<__half2*>(p1) = __floats2half2_rn(acc[mt][nt][2], acc[mt][nt][3]);
            }
    } else {
        const int ccol = (bn - 8) * BN + ccol_in;   // 0..2047 in g_fr row
        #pragma unroll
        for (int mt = 0; mt < 2; mt++)
            #pragma unroll
            for (int nt = 0; nt < 8; nt++) {
                __half* p0 = g_fr + (size_t)(crow + mt * 16)     * (2 * DIM) + ccol + nt * 8;
                __half* p1 = g_fr + (size_t)(crow + mt * 16 + 8) * (2 * DIM) + ccol + nt * 8;
                *reinterpret_cast<__half2*>(p0) = __floats2half2_rn(acc[mt][nt][0], acc[mt][nt][1]);
                *reinterpret_cast<__half2*>(p1) = __floats2half2_rn(acc[mt][nt][2], acc[mt][nt][3]);
            }
    }
}

// ---------------------------------------------------------------------------
// Kernel 3a: per-chunk (P,q).  x4, 128-thread blocks -> grid 1024.
// ---------------------------------------------------------------------------
__global__ void __launch_bounds__(128) scanA_kernel()
{
    int gid4 = blockIdx.x * blockDim.x + threadIdx.x;
    int chunk = gid4 / (BD / 4);
    int cd4 = gid4 % (BD / 4);
    int b = cd4 / (DIM / 4);
    int d = (cd4 % (DIM / 4)) * 4;

    float P[4] = {1.0f, 1.0f, 1.0f, 1.0f};
    float q[4] = {0.0f, 0.0f, 0.0f, 0.0f};
    int l0 = chunk * CHUNK;
    #pragma unroll 4
    for (int i = 0; i < CHUNK; i++) {
        int m = (l0 + i) * BATCH + b;
        uint2 uraw = *reinterpret_cast<const uint2*>(g_u_hf + (size_t)m * DIM + d);
        uint2 fraw = *reinterpret_cast<const uint2*>(g_fr + (size_t)m * (2 * DIM) + d);
        float2 u01 = __half22float2(*reinterpret_cast<__half2*>(&uraw.x));
        float2 u23 = __half22float2(*reinterpret_cast<__half2*>(&uraw.y));
        float2 f01 = __half22float2(*reinterpret_cast<__half2*>(&fraw.x));
        float2 f23 = __half22float2(*reinterpret_cast<__half2*>(&fraw.y));
        float uv[4] = {u01.x, u01.y, u23.x, u23.y};
        float fv[4] = {f01.x, f01.y, f23.x, f23.y};
        #pragma unroll
        for (int j = 0; j < 4; j++) {
            float fg = sigmoid_f(fv[j]);
            q[j] = fg * q[j] + (1.0f - fg) * uv[j];
            P[j] *= fg;
        }
    }
    int o = chunk * BD + b * DIM + d;
    *reinterpret_cast<float4*>(g_scanP + o) = make_float4(P[0], P[1], P[2], P[3]);
    *reinterpret_cast<float4*>(g_scanQ + o) = make_float4(q[0], q[1], q[2], q[3]);
}

// ---------------------------------------------------------------------------
// Kernel 3b: warp-per-channel affine scan, smem-staged for coalescing.
// Block: 256 threads = 8 warps = 8 channels. grid = BD/8 = 1024.
// ---------------------------------------------------------------------------
#define SB_CH 8
#define SB_PAD 9

__global__ void __launch_bounds__(256) scanB_kernel(
    const float* __restrict__ c0, float* __restrict__ out, int write_last_c)
{
    __shared__ float sP[NCHUNK * SB_PAD];
    __shared__ float sQ[NCHUNK * SB_PAD];
    __shared__ float sC[NCHUNK * SB_PAD];

    int tid = threadIdx.x;
    int ch_base = blockIdx.x * SB_CH;

    for (int i = tid; i < NCHUNK * SB_CH; i += 256) {
        int k = i >> 3, c = i & 7;
        sP[k * SB_PAD + c] = g_scanP[(size_t)k * BD + ch_base + c];
        sQ[k * SB_PAD + c] = g_scanQ[(size_t)k * BD + ch_base + c];
    }
    __syncthreads();

    int warp = tid >> 5;
    int lane = tid & 31;
    int c = warp;
    int k0 = 2 * lane;

    float P0 = sP[k0 * SB_PAD + c];
    float Q0 = sQ[k0 * SB_PAD + c];
    float P1 = sP[(k0 + 1) * SB_PAD + c];
    float Q1 = sQ[(k0 + 1) * SB_PAD + c];

    float sp = P1 * P0;
    float sq = P1 * Q0 + Q1;

    #pragma unroll
    for (int o = 1; o < 32; o <<= 1) {
        float pp = __shfl_up_sync(0xffffffffu, sp, o);
        float pq = __shfl_up_sync(0xffffffffu, sq, o);
        if (lane >= o) {
            sq = sp * pq + sq;
            sp = sp * pp;
        }
    }
    float ep = __shfl_up_sync(0xffffffffu, sp, 1);
    float eq = __shfl_up_sync(0xffffffffu, sq, 1);
    if (lane == 0) { ep = 1.0f; eq = 0.0f; }

    float cv = c0[ch_base + c];
    float cl = ep * cv + eq;
    sC[k0 * SB_PAD + c] = cl;
    sC[(k0 + 1) * SB_PAD + c] = P0 * cl + Q0;

    if (write_last_c && lane == 31)
        out[(size_t)MROWS * DIM + ch_base + c] = sp * cv + sq;

    __syncthreads();
    for (int i = tid; i < NCHUNK * SB_CH; i += 256) {
        int k = i >> 3, cc = i & 7;
        g_cin[(size_t)k * BD + ch_base + cc] = sC[k * SB_PAD + cc];
    }
}

// ---------------------------------------------------------------------------
// Kernel 3c: apply pass.  x4, 128-thread blocks -> grid 1024.
// ---------------------------------------------------------------------------
__global__ void __launch_bounds__(128) scanC_kernel(
    const float* __restrict__ x, float* __restrict__ out)
{
    int gid4 = blockIdx.x * blockDim.x + threadIdx.x;
    int chunk = gid4 / (BD / 4);
    int cd4 = gid4 % (BD / 4);
    int b = cd4 / (DIM / 4);
    int d = (cd4 % (DIM / 4)) * 4;

    int ci = chunk * BD + b * DIM + d;
    float4 cv4 = *reinterpret_cast<const float4*>(g_cin + ci);
    float cv[4] = {cv4.x, cv4.y, cv4.z, cv4.w};
    int l0 = chunk * CHUNK;
    #pragma unroll 4
    for (int i = 0; i < CHUNK; i++) {
        int m = (l0 + i) * BATCH + b;
        size_t frbase = (size_t)m * (2 * DIM);
        uint2 uraw = *reinterpret_cast<const uint2*>(g_u_hf + (size_t)m * DIM + d);
        uint2 fraw = *reinterpret_cast<const uint2*>(g_fr + frbase + d);
        uint2 rraw = *reinterpret_cast<const uint2*>(g_fr + frbase + DIM + d);
        uint2 nraw = *reinterpret_cast<const uint2*>(g_xn_hf + (size_t)m * DIM + d);
        size_t xi = (size_t)m * DIM + d;
        float4 xv = *reinterpret_cast<const float4*>(x + xi);

        float2 u01 = __half22float2(*reinterpret_cast<__half2*>(&uraw.x));
        float2 u23 = __half22float2(*reinterpret_cast<__half2*>(&uraw.y));
        float2 f01 = __half22float2(*reinterpret_cast<__half2*>(&fraw.x));
        float2 f23 = __half22float2(*reinterpret_cast<__half2*>(&fraw.y));
        float2 r01 = __half22float2(*reinterpret_cast<__half2*>(&rraw.x));
        float2 r23 = __half22float2(*reinterpret_cast<__half2*>(&rraw.y));
        float2 n01 = __half22float2(*reinterpret_cast<__half2*>(&nraw.x));
        float2 n23 = __half22float2(*reinterpret_cast<__half2*>(&nraw.y));

        float uv[4] = {u01.x, u01.y, u23.x, u23.y};
        float fv[4] = {f01.x, f01.y, f23.x, f23.y};
        float rv[4] = {r01.x, r01.y, r23.x, r23.y};
        float nv[4] = {n01.x, n01.y, n23.x, n23.y};
        float xvv[4] = {xv.x, xv.y, xv.z, xv.w};
        float ov[4];
        #pragma unroll
        for (int j = 0; j < 4; j++) {
            float fg = sigmoid_f(fv[j]);
            cv[j] = fg * cv[j] + (1.0f - fg) * uv[j];
            float rg = sigmoid_f(rv[j]);
            float h = rg * tanh_fast(cv[j]) + (1.0f - rg) * nv[j];
            ov[j] = xvv[j] + h;
        }
        *reinterpret_cast<float4*>(out + xi) = make_float4(ov[0], ov[1], ov[2], ov[3]);
    }
}

// ---------------------------------------------------------------------------
// Launch
// ---------------------------------------------------------------------------
extern "C" void kernel_launch(void* const* d_in, const int* in_sizes, int n_in,
                              void* d_out, int out_size)
{
    const float* x     = (const float*)d_in[0];
    const float* c0    = (const float*)d_in[1];
    const float* W     = (const float*)d_in[2];
    const float* gamma = (const float*)d_in[3];
    const float* beta  = (const float*)d_in[4];
    float* out = (float*)d_out;

    int write_last_c = (out_size >= MROWS * DIM + BD) ? 1 : 0;

    static int configured = 0;
    if (!configured) {
        cudaFuncSetAttribute(gemm_kernel, cudaFuncAttributeMaxDynamicSharedMemorySize,
                             GEMM_SMEM);
        configured = 1;
    }

    prep_kernel<<<LN_BLOCKS + WCONV_BLOCKS, 256>>>(x, gamma, beta, W);
    gemm_kernel<<<dim3(N3 / BN, MROWS / BM), 256, GEMM_SMEM>>>();
    scanA_kernel<<<(NCHUNK * BD / 4) / 128, 128>>>();
    scanB_kernel<<<BD / SB_CH, 256>>>(c0, out, write_last_c);
    scanC_kernel<<<(NCHUNK * BD / 4) / 128, 128>>>(x, out);
}

// round 16
// speedup vs baseline: 1.0379x; 1.0296x over previous
#include <cuda_runtime.h>
#include <cuda_fp16.h>
#include <math.h>
#include <stdint.h>

#define SEQ_L 2048
#define BATCH 8
#define DIM 1024
#define MROWS (SEQ_L * BATCH)   // 16384
#define N3 (3 * DIM)            // 3072
#define LN_EPS 1e-5f

#define CHUNK 32
#define NCHUNK (SEQ_L / CHUNK)  // 64  (= 2*warpSize, required by scanB)
#define BD (BATCH * DIM)        // 8192

// ---------------- scratch (allocation-free) ----------------
__device__ __half g_xn_hf[(size_t)MROWS * DIM];  // fp16 x_norm
__device__ __half g_w_hf[(size_t)N3 * DIM];      // fp16 W
__device__ __half g_u_hf[(size_t)MROWS * DIM];   // u fp16
__device__ __half g_fr[(size_t)MROWS * 2 * DIM]; // f,r fp16 (two contiguous halves per row)
__device__ float  g_scanP[NCHUNK * BD];
__device__ float  g_scanQ[NCHUNK * BD];
__device__ float  g_cin[NCHUNK * BD];

__device__ __forceinline__ float tanh_mufu(float x) {
    float y;
    asm("tanh.approx.f32 %0, %1;" : "=f"(y) : "f"(x));
    return y;
}
__device__ __forceinline__ float sigmoid_f(float v) {
    // sigmoid(v) = 0.5*tanh(v/2) + 0.5  (1 MUFU + 1 FMA)
    return fmaf(tanh_mufu(0.5f * v), 0.5f, 0.5f);
}

// ---------------------------------------------------------------------------
// Kernel 1: fused LayerNorm (blocks 0..2047) + W->fp16 (blocks 2048..5119)
// ---------------------------------------------------------------------------
#define LN_BLOCKS (MROWS / 8)                 // 2048
#define WCONV_BLOCKS ((N3 * DIM / 4) / 256)   // 3072

__global__ void __launch_bounds__(256) prep_kernel(
    const float* __restrict__ x,
    const float* __restrict__ gamma,
    const float* __restrict__ beta,
    const float* __restrict__ W)
{
    if (blockIdx.x >= LN_BLOCKS) {
        int i = (blockIdx.x - LN_BLOCKS) * blockDim.x + threadIdx.x;
        float4 v = reinterpret_cast<const float4*>(W)[i];
        __half2 h0 = __floats2half2_rn(v.x, v.y);
        __half2 h1 = __floats2half2_rn(v.z, v.w);
        uint2 packed;
        packed.x = *reinterpret_cast<uint32_t*>(&h0);
        packed.y = *reinterpret_cast<uint32_t*>(&h1);
        reinterpret_cast<uint2*>(g_w_hf)[i] = packed;
        return;
    }

    int warp = threadIdx.x >> 5;
    int lane = threadIdx.x & 31;
    int row = blockIdx.x * 8 + warp;

    const float4* xr = reinterpret_cast<const float4*>(x + (size_t)row * DIM);
    float4 v[8];
    #pragma unroll
    for (int j = 0; j < 8; j++) v[j] = xr[lane + j * 32];

    float s = 0.0f, s2 = 0.0f;
    #pragma unroll
    for (int j = 0; j < 8; j++) {
        s  += v[j].x + v[j].y + v[j].z + v[j].w;
        s2 += v[j].x*v[j].x + v[j].y*v[j].y + v[j].z*v[j].z + v[j].w*v[j].w;
    }
    #pragma unroll
    for (int o = 16; o > 0; o >>= 1) {
        s  += __shfl_xor_sync(0xffffffffu, s,  o);
        s2 += __shfl_xor_sync(0xffffffffu, s2, o);
    }
    float mean = s * (1.0f / DIM);
    float var  = s2 * (1.0f / DIM) - mean * mean;
    float inv  = rsqrtf(var + LN_EPS);

    uint2* orow = reinterpret_cast<uint2*>(g_xn_hf + (size_t)row * DIM);
    const float4* gp = reinterpret_cast<const float4*>(gamma);
    const float4* bp = reinterpret_cast<const float4*>(beta);
    #pragma unroll
    for (int j = 0; j < 8; j++) {
        float4 g = gp[lane + j * 32];
        float4 b = bp[lane + j * 32];
        float o0 = (v[j].x - mean) * inv * g.x + b.x;
        float o1 = (v[j].y - mean) * inv * g.y + b.y;
        float o2 = (v[j].z - mean) * inv * g.z + b.z;
        float o3 = (v[j].w - mean) * inv * g.w + b.w;
        __half2 h0 = __floats2half2_rn(o0, o1);
        __half2 h1 = __floats2half2_rn(o2, o3);
        uint2 packed;
        packed.x = *reinterpret_cast<uint32_t*>(&h0);
        packed.y = *reinterpret_cast<uint32_t*>(&h1);
        orow[lane + j * 32] = packed;
    }
}

// ---------------------------------------------------------------------------
// Kernel 2: fp16 mma.sync GEMM (frozen best-measured configuration)
// ---------------------------------------------------------------------------
#define BM 128
#define BN 128
#define BK 32
#define NSTAGE 5
#define KITER (DIM / BK)              // 32
#define TILE_A_BYTES (BM * BK * 2)
#define TILE_B_BYTES (BN * BK * 2)
#define STAGE_BYTES (TILE_A_BYTES + TILE_B_BYTES)  // 16384
#define GEMM_SMEM (NSTAGE * STAGE_BYTES)           // 81920

__device__ __forceinline__ uint32_t smem_u32(const void* p) {
    uint32_t a;
    asm("{ .reg .u64 t; cvta.to.shared.u64 t, %1; cvt.u32.u64 %0, t; }" : "=r"(a) : "l"(p));
    return a;
}
__device__ __forceinline__ uint32_t sw_off(int row, int c) {
    return (uint32_t)(row * 64 + ((c ^ (row & 3)) << 4));
}
__device__ __forceinline__ void cp_async16(uint32_t smem_addr, const void* gptr) {
    asm volatile("cp.async.cg.shared.global [%0], [%1], 16;"
                 :: "r"(smem_addr), "l"(gptr) : "memory");
}
__device__ __forceinline__ void cp_commit() {
    asm volatile("cp.async.commit_group;" ::: "memory");
}
__device__ __forceinline__ void cp_wait3() {
    asm volatile("cp.async.wait_group 3;" ::: "memory");
}
__device__ __forceinline__ void ldmatrix_x4(uint32_t* r, uint32_t addr) {
    asm volatile("ldmatrix.sync.aligned.m8n8.x4.shared.b16 {%0,%1,%2,%3}, [%4];"
                 : "=r"(r[0]), "=r"(r[1]), "=r"(r[2]), "=r"(r[3]) : "r"(addr));
}
__device__ __forceinline__ void mma16816(float* d, const uint32_t* a, const uint32_t* b) {
    asm volatile("mma.sync.aligned.m16n8k16.row.col.f32.f16.f16.f32 "
                 "{%0,%1,%2,%3}, {%4,%5,%6,%7}, {%8,%9}, {%0,%1,%2,%3};"
                 : "+f"(d[0]), "+f"(d[1]), "+f"(d[2]), "+f"(d[3])
                 : "r"(a[0]), "r"(a[1]), "r"(a[2]), "r"(a[3]), "r"(b[0]), "r"(b[1]));
}

__global__ void __launch_bounds__(256, 2) gemm_kernel()
{
    extern __shared__ char smem[];
    const int tid  = threadIdx.x;
    const int wid  = tid >> 5;
    const int lane = tid & 31;
    const int bn = blockIdx.x;   // 0..23
    const int bm = blockIdx.y;   // 0..127

    const int wm = wid & 3;
    const int wn = wid >> 2;

    const __half* Abase = g_xn_hf + (size_t)(bm * BM) * DIM;
    const __half* Bbase = g_w_hf  + (size_t)(bn * BN) * DIM;

    const int r0 = tid >> 1;
    const int cpair = (tid & 1) * 2;

    auto load_stage = [&](int kt, int st) {
        char* sa = smem + st * STAGE_BYTES;
        char* sb = sa + TILE_A_BYTES;
        const __half* ag = Abase + (size_t)r0 * DIM + kt * BK + cpair * 8;
        const __half* bg = Bbase + (size_t)r0 * DIM + kt * BK + cpair * 8;
        cp_async16(smem_u32(sa + sw_off(r0, cpair)),     ag);
        cp_async16(smem_u32(sa + sw_off(r0, cpair + 1)), ag + 8);
        cp_async16(smem_u32(sb + sw_off(r0, cpair)),     bg);
        cp_async16(smem_u32(sb + sw_off(r0, cpair + 1)), bg + 8);
    };

    float acc[2][8][4];
    #pragma unroll
    for (int i = 0; i < 2; i++)
        #pragma unroll
        for (int j = 0; j < 8; j++)
            #pragma unroll
            for (int k = 0; k < 4; k++) acc[i][j][k] = 0.0f;

    #pragma unroll
    for (int s = 0; s < NSTAGE - 1; s++) { load_stage(s, s); cp_commit(); }

    const int a_row_in_tile = lane & 15;
    const int a_chunk_half  = lane >> 4;
    const int b_row_in_pair = ((lane >> 4) << 3) + (lane & 7);
    const int b_chunk_half  = (lane >> 3) & 1;

    for (int kt = 0; kt < KITER; kt++) {
        cp_wait3();
        __syncthreads();

        int nkt = kt + NSTAGE - 1;
        if (nkt < KITER) load_stage(nkt, nkt % NSTAGE);
        cp_commit();

        char* sa = smem + (kt % NSTAGE) * STAGE_BYTES;
        char* sb = sa + TILE_A_BYTES;

        #pragma unroll
        for (int ks = 0; ks < 2; ks++) {
            uint32_t afr[2][4];
            #pragma unroll
            for (int mt = 0; mt < 2; mt++) {
                int row = wm * 32 + mt * 16 + a_row_in_tile;
                int c   = ks * 2 + a_chunk_half;
                ldmatrix_x4(afr[mt], smem_u32(sa + sw_off(row, c)));
            }
            uint32_t bfr[8][2];
            #pragma unroll
            for (int np = 0; np < 4; np++) {
                uint32_t r[4];
                int row = wn * 64 + np * 16 + b_row_in_pair;
                int c   = ks * 2 + b_chunk_half;
                ldmatrix_x4(r, smem_u32(sb + sw_off(row, c)));
                bfr[np * 2 + 0][0] = r[0]; bfr[np * 2 + 0][1] = r[1];
                bfr[np * 2 + 1][0] = r[2]; bfr[np * 2 + 1][1] = r[3];
            }
            #pragma unroll
            for (int mt = 0; mt < 2; mt++)
                #pragma unroll
                for (int nt = 0; nt < 8; nt++)
                    mma16816(acc[mt][nt], afr[mt], bfr[nt]);
        }
    }

    // epilogue: bn<8 -> u (fp16); else f/r (fp16, contiguous halves)
    const int crow = bm * BM + wm * 32 + (lane >> 2);
    const int ccol_in = wn * 64 + (lane & 3) * 2;
    if (bn < 8) {
        const int ccol = bn * BN + ccol_in;
        #pragma unroll
        for (int mt = 0; mt < 2; mt++)
            #pragma unroll
            for (int nt = 0; nt < 8; nt++) {
                __half* p0 = g_u_hf + (size_t)(crow + mt * 16)     * DIM + ccol + nt * 8;
                __half* p1 = g_u_hf + (size_t)(crow + mt * 16 + 8) * DIM + ccol + nt * 8;
                *reinterpret_cast<__half2*>(p0) = __floats2half2_rn(acc[mt][nt][0], acc[mt][nt][1]);
                *reinterpret_cast<__half2*>(p1) = __floats2half2_rn(acc[mt][nt][2], acc[mt][nt][3]);
            }
    } else {
        const int ccol = (bn - 8) * BN + ccol_in;
        #pragma unroll
        for (int mt = 0; mt < 2; mt++)
            #pragma unroll
            for (int nt = 0; nt < 8; nt++) {
                __half* p0 = g_fr + (size_t)(crow + mt * 16)     * (2 * DIM) + ccol + nt * 8;
                __half* p1 = g_fr + (size_t)(crow + mt * 16 + 8) * (2 * DIM) + ccol + nt * 8;
                *reinterpret_cast<__half2*>(p0) = __floats2half2_rn(acc[mt][nt][0], acc[mt][nt][1]);
                *reinterpret_cast<__half2*>(p1) = __floats2half2_rn(acc[mt][nt][2], acc[mt][nt][3]);
            }
    }
}

// ---------------------------------------------------------------------------
// Kernel 3a: per-chunk (P,q).  x4, 128-thread blocks -> grid 1024.
// ---------------------------------------------------------------------------
__global__ void __launch_bounds__(128) scanA_kernel()
{
    int gid4 = blockIdx.x * blockDim.x + threadIdx.x;
    int chunk = gid4 / (BD / 4);
    int cd4 = gid4 % (BD / 4);
    int b = cd4 / (DIM / 4);
    int d = (cd4 % (DIM / 4)) * 4;

    float P[4] = {1.0f, 1.0f, 1.0f, 1.0f};
    float q[4] = {0.0f, 0.0f, 0.0f, 0.0f};
    int l0 = chunk * CHUNK;
    #pragma unroll 4
    for (int i = 0; i < CHUNK; i++) {
        int m = (l0 + i) * BATCH + b;
        uint2 uraw = *reinterpret_cast<const uint2*>(g_u_hf + (size_t)m * DIM + d);
        uint2 fraw = *reinterpret_cast<const uint2*>(g_fr + (size_t)m * (2 * DIM) + d);
        float2 u01 = __half22float2(*reinterpret_cast<__half2*>(&uraw.x));
        float2 u23 = __half22float2(*reinterpret_cast<__half2*>(&uraw.y));
        float2 f01 = __half22float2(*reinterpret_cast<__half2*>(&fraw.x));
        float2 f23 = __half22float2(*reinterpret_cast<__half2*>(&fraw.y));
        float uv[4] = {u01.x, u01.y, u23.x, u23.y};
        float fv[4] = {f01.x, f01.y, f23.x, f23.y};
        #pragma unroll
        for (int j = 0; j < 4; j++) {
            float fg = sigmoid_f(fv[j]);
            q[j] = fg * q[j] + (1.0f - fg) * uv[j];
            P[j] *= fg;
        }
    }
    int o = chunk * BD + b * DIM + d;
    *reinterpret_cast<float4*>(g_scanP + o) = make_float4(P[0], P[1], P[2], P[3]);
    *reinterpret_cast<float4*>(g_scanQ + o) = make_float4(q[0], q[1], q[2], q[3]);
}

// ---------------------------------------------------------------------------
// Kernel 3b: warp-per-channel affine scan, smem-staged for coalescing.
// ---------------------------------------------------------------------------
#define SB_CH 8
#define SB_PAD 9

__global__ void __launch_bounds__(256) scanB_kernel(
    const float* __restrict__ c0, float* __restrict__ out, int write_last_c)
{
    __shared__ float sP[NCHUNK * SB_PAD];
    __shared__ float sQ[NCHUNK * SB_PAD];
    __shared__ float sC[NCHUNK * SB_PAD];

    int tid = threadIdx.x;
    int ch_base = blockIdx.x * SB_CH;

    for (int i = tid; i < NCHUNK * SB_CH; i += 256) {
        int k = i >> 3, c = i & 7;
        sP[k * SB_PAD + c] = g_scanP[(size_t)k * BD + ch_base + c];
        sQ[k * SB_PAD + c] = g_scanQ[(size_t)k * BD + ch_base + c];
    }
    __syncthreads();

    int warp = tid >> 5;
    int lane = tid & 31;
    int c = warp;
    int k0 = 2 * lane;

    float P0 = sP[k0 * SB_PAD + c];
    float Q0 = sQ[k0 * SB_PAD + c];
    float P1 = sP[(k0 + 1) * SB_PAD + c];
    float Q1 = sQ[(k0 + 1) * SB_PAD + c];

    float sp = P1 * P0;
    float sq = P1 * Q0 + Q1;

    #pragma unroll
    for (int o = 1; o < 32; o <<= 1) {
        float pp = __shfl_up_sync(0xffffffffu, sp, o);
        float pq = __shfl_up_sync(0xffffffffu, sq, o);
        if (lane >= o) {
            sq = sp * pq + sq;
            sp = sp * pp;
        }
    }
    float ep = __shfl_up_sync(0xffffffffu, sp, 1);
    float eq = __shfl_up_sync(0xffffffffu, sq, 1);
    if (lane == 0) { ep = 1.0f; eq = 0.0f; }

    float cv = c0[ch_base + c];
    float cl = ep * cv + eq;
    sC[k0 * SB_PAD + c] = cl;
    sC[(k0 + 1) * SB_PAD + c] = P0 * cl + Q0;

    if (write_last_c && lane == 31)
        out[(size_t)MROWS * DIM + ch_base + c] = sp * cv + sq;

    __syncthreads();
    for (int i = tid; i < NCHUNK * SB_CH; i += 256) {
        int k = i >> 3, cc = i & 7;
        g_cin[(size_t)k * BD + ch_base + cc] = sC[k * SB_PAD + cc];
    }
}

// ---------------------------------------------------------------------------
// Kernel 3c: apply pass.  x4, 128-thread blocks -> grid 1024.
// ---------------------------------------------------------------------------
__global__ void __launch_bounds__(128) scanC_kernel(
    const float* __restrict__ x, float* __restrict__ out)
{
    int gid4 = blockIdx.x * blockDim.x + threadIdx.x;
    int chunk = gid4 / (BD / 4);
    int cd4 = gid4 % (BD / 4);
    int b = cd4 / (DIM / 4);
    int d = (cd4 % (DIM / 4)) * 4;

    int ci = chunk * BD + b * DIM + d;
    float4 cv4 = *reinterpret_cast<const float4*>(g_cin + ci);
    float cv[4] = {cv4.x, cv4.y, cv4.z, cv4.w};
    int l0 = chunk * CHUNK;
    #pragma unroll 4
    for (int i = 0; i < CHUNK; i++) {
        int m = (l0 + i) * BATCH + b;
        size_t frbase = (size_t)m * (2 * DIM);
        uint2 uraw = *reinterpret_cast<const uint2*>(g_u_hf + (size_t)m * DIM + d);
        uint2 fraw = *reinterpret_cast<const uint2*>(g_fr + frbase + d);
        uint2 rraw = *reinterpret_cast<const uint2*>(g_fr + frbase + DIM + d);
        uint2 nraw = *reinterpret_cast<const uint2*>(g_xn_hf + (size_t)m * DIM + d);
        size_t xi = (size_t)m * DIM + d;
        float4 xv = *reinterpret_cast<const float4*>(x + xi);

        float2 u01 = __half22float2(*reinterpret_cast<__half2*>(&uraw.x));
        float2 u23 = __half22float2(*reinterpret_cast<__half2*>(&uraw.y));
        float2 f01 = __half22float2(*reinterpret_cast<__half2*>(&fraw.x));
        float2 f23 = __half22float2(*reinterpret_cast<__half2*>(&fraw.y));
        float2 r01 = __half22float2(*reinterpret_cast<__half2*>(&rraw.x));
        float2 r23 = __half22float2(*reinterpret_cast<__half2*>(&rraw.y));
        float2 n01 = __half22float2(*reinterpret_cast<__half2*>(&nraw.x));
        float2 n23 = __half22float2(*reinterpret_cast<__half2*>(&nraw.y));

        float uv[4] = {u01.x, u01.y, u23.x, u23.y};
        float fv[4] = {f01.x, f01.y, f23.x, f23.y};
        float rv[4] = {r01.x, r01.y, r23.x, r23.y};
        float nv[4] = {n01.x, n01.y, n23.x, n23.y};
        float xvv[4] = {xv.x, xv.y, xv.z, xv.w};
        float ov[4];
        #pragma unroll
        for (int j = 0; j < 4; j++) {
            float fg = sigmoid_f(fv[j]);
            cv[j] = fg * cv[j] + (1.0f - fg) * uv[j];
            float rg = sigmoid_f(rv[j]);
            float h = rg * tanh_mufu(cv[j]) + (1.0f - rg) * nv[j];
            ov[j] = xvv[j] + h;
        }
        *reinterpret_cast<float4*>(out + xi) = make_float4(ov[0], ov[1], ov[2], ov[3]);
    }
}

// ---------------------------------------------------------------------------
// Launch
// ---------------------------------------------------------------------------
extern "C" void kernel_launch(void* const* d_in, const int* in_sizes, int n_in,
                              void* d_out, int out_size)
{
    const float* x     = (const float*)d_in[0];
    const float* c0    = (const float*)d_in[1];
    const float* W     = (const float*)d_in[2];
    const float* gamma = (const float*)d_in[3];
    const float* beta  = (const float*)d_in[4];
    float* out = (float*)d_out;

    int write_last_c = (out_size >= MROWS * DIM + BD) ? 1 : 0;

    static int configured = 0;
    if (!configured) {
        cudaFuncSetAttribute(gemm_kernel, cudaFuncAttributeMaxDynamicSharedMemorySize,
                             GEMM_SMEM);
        configured = 1;
    }

    prep_kernel<<<LN_BLOCKS + WCONV_BLOCKS, 256>>>(x, gamma, beta, W);
    gemm_kernel<<<dim3(N3 / BN, MROWS / BM), 256, GEMM_SMEM>>>();
    scanA_kernel<<<(NCHUNK * BD / 4) / 128, 128>>>();
    scanB_kernel<<<BD / SB_CH, 256>>>(c0, out, write_last_c);
    scanC_kernel<<<(NCHUNK * BD / 4) / 128, 128>>>(x, out);
}

// round 17
// speedup vs baseline: 1.0609x; 1.0221x over previous
#include <cuda_runtime.h>
#include <cuda_fp16.h>
#include <math.h>
#include <stdint.h>

#define SEQ_L 2048
#define BATCH 8
#define DIM 1024
#define MROWS (SEQ_L * BATCH)   // 16384
#define N3 (3 * DIM)            // 3072
#define LN_EPS 1e-5f

#define CHUNK 32
#define NCHUNK (SEQ_L / CHUNK)  // 64  (= 2*warpSize, required by scanB)
#define BD (BATCH * DIM)        // 8192

// ---------------- scratch (allocation-free) ----------------
__device__ __half g_xn_hf[(size_t)MROWS * DIM];  // fp16 x_norm
__device__ __half g_w_hf[(size_t)N3 * DIM];      // fp16 W
__device__ __half g_u_hf[(size_t)MROWS * DIM];   // u fp16
__device__ __half g_fr[(size_t)MROWS * 2 * DIM]; // f,r fp16 (two contiguous halves per row)
__device__ float  g_scanP[NCHUNK * BD];
__device__ float  g_scanQ[NCHUNK * BD];
__device__ float  g_cin[NCHUNK * BD];

__device__ __forceinline__ float tanh_mufu(float x) {
    float y;
    asm("tanh.approx.f32 %0, %1;" : "=f"(y) : "f"(x));
    return y;
}
__device__ __forceinline__ float sigmoid_f(float v) {
    return fmaf(tanh_mufu(0.5f * v), 0.5f, 0.5f);
}

// ---------------------------------------------------------------------------
// Kernel 1: fused LayerNorm (blocks 0..2047) + W->fp16 (blocks 2048..5119)
// ---------------------------------------------------------------------------
#define LN_BLOCKS (MROWS / 8)                 // 2048
#define WCONV_BLOCKS ((N3 * DIM / 4) / 256)   // 3072

__global__ void __launch_bounds__(256) prep_kernel(
    const float* __restrict__ x,
    const float* __restrict__ gamma,
    const float* __restrict__ beta,
    const float* __restrict__ W)
{
    if (blockIdx.x >= LN_BLOCKS) {
        int i = (blockIdx.x - LN_BLOCKS) * blockDim.x + threadIdx.x;
        float4 v = reinterpret_cast<const float4*>(W)[i];
        __half2 h0 = __floats2half2_rn(v.x, v.y);
        __half2 h1 = __floats2half2_rn(v.z, v.w);
        uint2 packed;
        packed.x = *reinterpret_cast<uint32_t*>(&h0);
        packed.y = *reinterpret_cast<uint32_t*>(&h1);
        reinterpret_cast<uint2*>(g_w_hf)[i] = packed;
        return;
    }

    int warp = threadIdx.x >> 5;
    int lane = threadIdx.x & 31;
    int row = blockIdx.x * 8 + warp;

    const float4* xr = reinterpret_cast<const float4*>(x + (size_t)row * DIM);
    float4 v[8];
    #pragma unroll
    for (int j = 0; j < 8; j++) v[j] = xr[lane + j * 32];

    float s = 0.0f, s2 = 0.0f;
    #pragma unroll
    for (int j = 0; j < 8; j++) {
        s  += v[j].x + v[j].y + v[j].z + v[j].w;
        s2 += v[j].x*v[j].x + v[j].y*v[j].y + v[j].z*v[j].z + v[j].w*v[j].w;
    }
    #pragma unroll
    for (int o = 16; o > 0; o >>= 1) {
        s  += __shfl_xor_sync(0xffffffffu, s,  o);
        s2 += __shfl_xor_sync(0xffffffffu, s2, o);
    }
    float mean = s * (1.0f / DIM);
    float var  = s2 * (1.0f / DIM) - mean * mean;
    float inv  = rsqrtf(var + LN_EPS);

    uint2* orow = reinterpret_cast<uint2*>(g_xn_hf + (size_t)row * DIM);
    const float4* gp = reinterpret_cast<const float4*>(gamma);
    const float4* bp = reinterpret_cast<const float4*>(beta);
    #pragma unroll
    for (int j = 0; j < 8; j++) {
        float4 g = gp[lane + j * 32];
        float4 b = bp[lane + j * 32];
        float o0 = (v[j].x - mean) * inv * g.x + b.x;
        float o1 = (v[j].y - mean) * inv * g.y + b.y;
        float o2 = (v[j].z - mean) * inv * g.z + b.z;
        float o3 = (v[j].w - mean) * inv * g.w + b.w;
        __half2 h0 = __floats2half2_rn(o0, o1);
        __half2 h1 = __floats2half2_rn(o2, o3);
        uint2 packed;
        packed.x = *reinterpret_cast<uint32_t*>(&h0);
        packed.y = *reinterpret_cast<uint32_t*>(&h1);
        orow[lane + j * 32] = packed;
    }
}

// ---------------------------------------------------------------------------
// Kernel 2: fp16 mma.sync GEMM (frozen config; bn_base param for split launch)
// ---------------------------------------------------------------------------
#define BM 128
#define BN 128
#define BK 32
#define NSTAGE 5
#define KITER (DIM / BK)              // 32
#define TILE_A_BYTES (BM * BK * 2)
#define TILE_B_BYTES (BN * BK * 2)
#define STAGE_BYTES (TILE_A_BYTES + TILE_B_BYTES)  // 16384
#define GEMM_SMEM (NSTAGE * STAGE_BYTES)           // 81920

__device__ __forceinline__ uint32_t smem_u32(const void* p) {
    uint32_t a;
    asm("{ .reg .u64 t; cvta.to.shared.u64 t, %1; cvt.u32.u64 %0, t; }" : "=r"(a) : "l"(p));
    return a;
}
__device__ __forceinline__ uint32_t sw_off(int row, int c) {
    return (uint32_t)(row * 64 + ((c ^ (row & 3)) << 4));
}
__device__ __forceinline__ void cp_async16(uint32_t smem_addr, const void* gptr) {
    asm volatile("cp.async.cg.shared.global [%0], [%1], 16;"
                 :: "r"(smem_addr), "l"(gptr) : "memory");
}
__device__ __forceinline__ void cp_commit() {
    asm volatile("cp.async.commit_group;" ::: "memory");
}
__device__ __forceinline__ void cp_wait3() {
    asm volatile("cp.async.wait_group 3;" ::: "memory");
}
__device__ __forceinline__ void ldmatrix_x4(uint32_t* r, uint32_t addr) {
    asm volatile("ldmatrix.sync.aligned.m8n8.x4.shared.b16 {%0,%1,%2,%3}, [%4];"
                 : "=r"(r[0]), "=r"(r[1]), "=r"(r[2]), "=r"(r[3]) : "r"(addr));
}
__device__ __forceinline__ void mma16816(float* d, const uint32_t* a, const uint32_t* b) {
    asm volatile("mma.sync.aligned.m16n8k16.row.col.f32.f16.f16.f32 "
                 "{%0,%1,%2,%3}, {%4,%5,%6,%7}, {%8,%9}, {%0,%1,%2,%3};"
                 : "+f"(d[0]), "+f"(d[1]), "+f"(d[2]), "+f"(d[3])
                 : "r"(a[0]), "r"(a[1]), "r"(a[2]), "r"(a[3]), "r"(b[0]), "r"(b[1]));
}

__global__ void __launch_bounds__(256, 2) gemm_kernel(int bn_base)
{
    extern __shared__ char smem[];
    const int tid  = threadIdx.x;
    const int wid  = tid >> 5;
    const int lane = tid & 31;
    const int bn = blockIdx.x + bn_base;   // 0..23
    const int bm = blockIdx.y;             // 0..127

    const int wm = wid & 3;
    const int wn = wid >> 2;

    const __half* Abase = g_xn_hf + (size_t)(bm * BM) * DIM;
    const __half* Bbase = g_w_hf  + (size_t)(bn * BN) * DIM;

    const int r0 = tid >> 1;
    const int cpair = (tid & 1) * 2;

    auto load_stage = [&](int kt, int st) {
        char* sa = smem + st * STAGE_BYTES;
        char* sb = sa + TILE_A_BYTES;
        const __half* ag = Abase + (size_t)r0 * DIM + kt * BK + cpair * 8;
        const __half* bg = Bbase + (size_t)r0 * DIM + kt * BK + cpair * 8;
        cp_async16(smem_u32(sa + sw_off(r0, cpair)),     ag);
        cp_async16(smem_u32(sa + sw_off(r0, cpair + 1)), ag + 8);
        cp_async16(smem_u32(sb + sw_off(r0, cpair)),     bg);
        cp_async16(smem_u32(sb + sw_off(r0, cpair + 1)), bg + 8);
    };

    float acc[2][8][4];
    #pragma unroll
    for (int i = 0; i < 2; i++)
        #pragma unroll
        for (int j = 0; j < 8; j++)
            #pragma unroll
            for (int k = 0; k < 4; k++) acc[i][j][k] = 0.0f;

    #pragma unroll
    for (int s = 0; s < NSTAGE - 1; s++) { load_stage(s, s); cp_commit(); }

    const int a_row_in_tile = lane & 15;
    const int a_chunk_half  = lane >> 4;
    const int b_row_in_pair = ((lane >> 4) << 3) + (lane & 7);
    const int b_chunk_half  = (lane >> 3) & 1;

    for (int kt = 0; kt < KITER; kt++) {
        cp_wait3();
        __syncthreads();

        int nkt = kt + NSTAGE - 1;
        if (nkt < KITER) load_stage(nkt, nkt % NSTAGE);
        cp_commit();

        char* sa = smem + (kt % NSTAGE) * STAGE_BYTES;
        char* sb = sa + TILE_A_BYTES;

        #pragma unroll
        for (int ks = 0; ks < 2; ks++) {
            uint32_t afr[2][4];
            #pragma unroll
            for (int mt = 0; mt < 2; mt++) {
                int row = wm * 32 + mt * 16 + a_row_in_tile;
                int c   = ks * 2 + a_chunk_half;
                ldmatrix_x4(afr[mt], smem_u32(sa + sw_off(row, c)));
            }
            uint32_t bfr[8][2];
            #pragma unroll
            for (int np = 0; np < 4; np++) {
                uint32_t r[4];
                int row = wn * 64 + np * 16 + b_row_in_pair;
                int c   = ks * 2 + b_chunk_half;
                ldmatrix_x4(r, smem_u32(sb + sw_off(row, c)));
                bfr[np * 2 + 0][0] = r[0]; bfr[np * 2 + 0][1] = r[1];
                bfr[np * 2 + 1][0] = r[2]; bfr[np * 2 + 1][1] = r[3];
            }
            #pragma unroll
            for (int mt = 0; mt < 2; mt++)
                #pragma unroll
                for (int nt = 0; nt < 8; nt++)
                    mma16816(acc[mt][nt], afr[mt], bfr[nt]);
        }
    }

    // epilogue: bn<8 -> u (fp16); else f/r (fp16, contiguous halves)
    const int crow = bm * BM + wm * 32 + (lane >> 2);
    const int ccol_in = wn * 64 + (lane & 3) * 2;
    if (bn < 8) {
        const int ccol = bn * BN + ccol_in;
        #pragma unroll
        for (int mt = 0; mt < 2; mt++)
            #pragma unroll
            for (int nt = 0; nt < 8; nt++) {
                __half* p0 = g_u_hf + (size_t)(crow + mt * 16)     * DIM + ccol + nt * 8;
                __half* p1 = g_u_hf + (size_t)(crow + mt * 16 + 8) * DIM + ccol + nt * 8;
                *reinterpret_cast<__half2*>(p0) = __floats2half2_rn(acc[mt][nt][0], acc[mt][nt][1]);
                *reinterpret_cast<__half2*>(p1) = __floats2half2_rn(acc[mt][nt][2], acc[mt][nt][3]);
            }
    } else {
        const int ccol = (bn - 8) * BN + ccol_in;   // f: 0..1023, r: 1024..2047
        #pragma unroll
        for (int mt = 0; mt < 2; mt++)
            #pragma unroll
            for (int nt = 0; nt < 8; nt++) {
                __half* p0 = g_fr + (size_t)(crow + mt * 16)     * (2 * DIM) + ccol + nt * 8;
                __half* p1 = g_fr + (size_t)(crow + mt * 16 + 8) * (2 * DIM) + ccol + nt * 8;
                *reinterpret_cast<__half2*>(p0) = __floats2half2_rn(acc[mt][nt][0], acc[mt][nt][1]);
                *reinterpret_cast<__half2*>(p1) = __floats2half2_rn(acc[mt][nt][2], acc[mt][nt][3]);
            }
    }
}

// ---------------------------------------------------------------------------
// Kernel 3a: per-chunk (P,q).  x4, 128-thread blocks -> grid 1024.
// ---------------------------------------------------------------------------
__global__ void __launch_bounds__(128) scanA_kernel()
{
    int gid4 = blockIdx.x * blockDim.x + threadIdx.x;
    int chunk = gid4 / (BD / 4);
    int cd4 = gid4 % (BD / 4);
    int b = cd4 / (DIM / 4);
    int d = (cd4 % (DIM / 4)) * 4;

    float P[4] = {1.0f, 1.0f, 1.0f, 1.0f};
    float q[4] = {0.0f, 0.0f, 0.0f, 0.0f};
    int l0 = chunk * CHUNK;
    #pragma unroll 4
    for (int i = 0; i < CHUNK; i++) {
        int m = (l0 + i) * BATCH + b;
        uint2 uraw = *reinterpret_cast<const uint2*>(g_u_hf + (size_t)m * DIM + d);
        uint2 fraw = *reinterpret_cast<const uint2*>(g_fr + (size_t)m * (2 * DIM) + d);
        float2 u01 = __half22float2(*reinterpret_cast<__half2*>(&uraw.x));
        float2 u23 = __half22float2(*reinterpret_cast<__half2*>(&uraw.y));
        float2 f01 = __half22float2(*reinterpret_cast<__half2*>(&fraw.x));
        float2 f23 = __half22float2(*reinterpret_cast<__half2*>(&fraw.y));
        float uv[4] = {u01.x, u01.y, u23.x, u23.y};
        float fv[4] = {f01.x, f01.y, f23.x, f23.y};
        #pragma unroll
        for (int j = 0; j < 4; j++) {
            float fg = sigmoid_f(fv[j]);
            q[j] = fg * q[j] + (1.0f - fg) * uv[j];
            P[j] *= fg;
        }
    }
    int o = chunk * BD + b * DIM + d;
    *reinterpret_cast<float4*>(g_scanP + o) = make_float4(P[0], P[1], P[2], P[3]);
    *reinterpret_cast<float4*>(g_scanQ + o) = make_float4(q[0], q[1], q[2], q[3]);
}

// ---------------------------------------------------------------------------
// Kernel 3b: warp-per-channel affine scan, smem-staged for coalescing.
// ---------------------------------------------------------------------------
#define SB_CH 8
#define SB_PAD 9

__global__ void __launch_bounds__(256) scanB_kernel(
    const float* __restrict__ c0, float* __restrict__ out, int write_last_c)
{
    __shared__ float sP[NCHUNK * SB_PAD];
    __shared__ float sQ[NCHUNK * SB_PAD];
    __shared__ float sC[NCHUNK * SB_PAD];

    int tid = threadIdx.x;
    int ch_base = blockIdx.x * SB_CH;

    for (int i = tid; i < NCHUNK * SB_CH; i += 256) {
        int k = i >> 3, c = i & 7;
        sP[k * SB_PAD + c] = g_scanP[(size_t)k * BD + ch_base + c];
        sQ[k * SB_PAD + c] = g_scanQ[(size_t)k * BD + ch_base + c];
    }
    __syncthreads();

    int warp = tid >> 5;
    int lane = tid & 31;
    int c = warp;
    int k0 = 2 * lane;

    float P0 = sP[k0 * SB_PAD + c];
    float Q0 = sQ[k0 * SB_PAD + c];
    float P1 = sP[(k0 + 1) * SB_PAD + c];
    float Q1 = sQ[(k0 + 1) * SB_PAD + c];

    float sp = P1 * P0;
    float sq = P1 * Q0 + Q1;

    #pragma unroll
    for (int o = 1; o < 32; o <<= 1) {
        float pp = __shfl_up_sync(0xffffffffu, sp, o);
        float pq = __shfl_up_sync(0xffffffffu, sq, o);
        if (lane >= o) {
            sq = sp * pq + sq;
            sp = sp * pp;
        }
    }
    float ep = __shfl_up_sync(0xffffffffu, sp, 1);
    float eq = __shfl_up_sync(0xffffffffu, sq, 1);
    if (lane == 0) { ep = 1.0f; eq = 0.0f; }

    float cv = c0[ch_base + c];
    float cl = ep * cv + eq;
    sC[k0 * SB_PAD + c] = cl;
    sC[(k0 + 1) * SB_PAD + c] = P0 * cl + Q0;

    if (write_last_c && lane == 31)
        out[(size_t)MROWS * DIM + ch_base + c] = sp * cv + sq;

    __syncthreads();
    for (int i = tid; i < NCHUNK * SB_CH; i += 256) {
        int k = i >> 3, cc = i & 7;
        g_cin[(size_t)k * BD + ch_base + cc] = sC[k * SB_PAD + cc];
    }
}

// ---------------------------------------------------------------------------
// Kernel 3c: apply pass.  x4, 128-thread blocks -> grid 1024.
// ---------------------------------------------------------------------------
__global__ void __launch_bounds__(128) scanC_kernel(
    const float* __restrict__ x, float* __restrict__ out)
{
    int gid4 = blockIdx.x * blockDim.x + threadIdx.x;
    int chunk = gid4 / (BD / 4);
    int cd4 = gid4 % (BD / 4);
    int b = cd4 / (DIM / 4);
    int d = (cd4 % (DIM / 4)) * 4;

    int ci = chunk * BD + b * DIM + d;
    float4 cv4 = *reinterpret_cast<const float4*>(g_cin + ci);
    float cv[4] = {cv4.x, cv4.y, cv4.z, cv4.w};
    int l0 = chunk * CHUNK;
    #pragma unroll 4
    for (int i = 0; i < CHUNK; i++) {
        int m = (l0 + i) * BATCH + b;
        size_t frbase = (size_t)m * (2 * DIM);
        uint2 uraw = *reinterpret_cast<const uint2*>(g_u_hf + (size_t)m * DIM + d);
        uint2 fraw = *reinterpret_cast<const uint2*>(g_fr + frbase + d);
        uint2 rraw = *reinterpret_cast<const uint2*>(g_fr + frbase + DIM + d);
        uint2 nraw = *reinterpret_cast<const uint2*>(g_xn_hf + (size_t)m * DIM + d);
        size_t xi = (size_t)m * DIM + d;
        float4 xv = *reinterpret_cast<const float4*>(x + xi);

        float2 u01 = __half22float2(*reinterpret_cast<__half2*>(&uraw.x));
        float2 u23 = __half22float2(*reinterpret_cast<__half2*>(&uraw.y));
        float2 f01 = __half22float2(*reinterpret_cast<__half2*>(&fraw.x));
        float2 f23 = __half22float2(*reinterpret_cast<__half2*>(&fraw.y));
        float2 r01 = __half22float2(*reinterpret_cast<__half2*>(&rraw.x));
        float2 r23 = __half22float2(*reinterpret_cast<__half2*>(&rraw.y));
        float2 n01 = __half22float2(*reinterpret_cast<__half2*>(&nraw.x));
        float2 n23 = __half22float2(*reinterpret_cast<__half2*>(&nraw.y));

        float uv[4] = {u01.x, u01.y, u23.x, u23.y};
        float fv[4] = {f01.x, f01.y, f23.x, f23.y};
        float rv[4] = {r01.x, r01.y, r23.x, r23.y};
        float nv[4] = {n01.x, n01.y, n23.x, n23.y};
        float xvv[4] = {xv.x, xv.y, xv.z, xv.w};
        float ov[4];
        #pragma unroll
        for (int j = 0; j < 4; j++) {
            float fg = sigmoid_f(fv[j]);
            cv[j] = fg * cv[j] + (1.0f - fg) * uv[j];
            float rg = sigmoid_f(rv[j]);
            float h = rg * tanh_mufu(cv[j]) + (1.0f - rg) * nv[j];
            ov[j] = xvv[j] + h;
        }
        *reinterpret_cast<float4*>(out + xi) = make_float4(ov[0], ov[1], ov[2], ov[3]);
    }
}

// ---------------------------------------------------------------------------
// Launch: fork gemm_r onto a second stream, overlap with scanA+scanB
// ---------------------------------------------------------------------------
extern "C" void kernel_launch(void* const* d_in, const int* in_sizes, int n_in,
                              void* d_out, int out_size)
{
    const float* x     = (const float*)d_in[0];
    const float* c0    = (const float*)d_in[1];
    const float* W     = (const float*)d_in[2];
    const float* gamma = (const float*)d_in[3];
    const float* beta  = (const float*)d_in[4];
    float* out = (float*)d_out;

    int write_last_c = (out_size >= MROWS * DIM + BD) ? 1 : 0;

    static int configured = 0;
    static cudaStream_t s2;
    static cudaEvent_t evFork, evJoin;
    if (!configured) {
        cudaFuncSetAttribute(gemm_kernel, cudaFuncAttributeMaxDynamicSharedMemorySize,
                             GEMM_SMEM);
        cudaStreamCreateWithFlags(&s2, cudaStreamNonBlocking);
        cudaEventCreateWithFlags(&evFork, cudaEventDisableTiming);
        cudaEventCreateWithFlags(&evJoin, cudaEventDisableTiming);
        configured = 1;
    }

    prep_kernel<<<LN_BLOCKS + WCONV_BLOCKS, 256>>>(x, gamma, beta, W);
    // u + f columns (bn 0..15)
    gemm_kernel<<<dim3(16, MROWS / BM), 256, GEMM_SMEM>>>(0);

    // fork: r columns (bn 16..23) on s2, concurrent with scanA+scanB
    cudaEventRecord(evFork, 0);
    cudaStreamWaitEvent(s2, evFork, 0);
    gemm_kernel<<<dim3(8, MROWS / BM), 256, GEMM_SMEM, s2>>>(16);
    cudaEventRecord(evJoin, s2);

    scanA_kernel<<<(NCHUNK * BD / 4) / 128, 128>>>();
    scanB_kernel<<<BD / SB_CH, 256>>>(c0, out, write_last_c);

    // join: scanC needs r
    cudaStreamWaitEvent(0, evJoin, 0);
    scanC_kernel<<<(NCHUNK * BD / 4) / 128, 128>>>(x, out);
}